// round 4
// baseline (speedup 1.0000x reference)
#include <cuda_runtime.h>

#define NROWS 16384
#define DCOLS 2048
#define TPB   256
#define GRID  1024                       // 8 warps/CTA * 1024 = 8192 warps
#define WARPS_TOTAL (GRID * 8)           // each warp: exactly 2 rows

// Device-global scratch (no allocations allowed).
__device__ float        g_partial[GRID];
__device__ unsigned int g_counter = 0;   // self-resetting for graph replay

__global__ void __launch_bounds__(TPB) cosine_loss_persistent(
    const float* __restrict__ cxr, const float* __restrict__ ehr,
    float* __restrict__ out)
{
    const int t    = threadIdx.x;
    const int lane = t & 31;
    const int warp = t >> 5;
    const int gw   = blockIdx.x * 8 + warp;   // global warp id, 0..8191

    float csum = 0.f;   // cos(row gw) + cos(row gw+8192), fixed order

    #pragma unroll
    for (int r = 0; r < 2; r++) {
        const int row = gw + r * WARPS_TOTAL;
        const float4* __restrict__ a = reinterpret_cast<const float4*>(ehr + (size_t)row * DCOLS);
        const float4* __restrict__ b = reinterpret_cast<const float4*>(cxr + (size_t)row * DCOLS);

        float dot = 0.f, na = 0.f, nb = 0.f;

        // 512 float4 per tensor per row; 32 lanes -> 16 float4 each.
        // 8 chunks of (2 float4 per tensor), 4 loads front-batched (MLP=4).
        #pragma unroll
        for (int c = 0; c < 8; c++) {
            float4 a0 = a[lane + 64 * c];
            float4 b0 = b[lane + 64 * c];
            float4 a1 = a[lane + 64 * c + 32];
            float4 b1 = b[lane + 64 * c + 32];

            dot += a0.x*b0.x + a0.y*b0.y + a0.z*b0.z + a0.w*b0.w;
            na  += a0.x*a0.x + a0.y*a0.y + a0.z*a0.z + a0.w*a0.w;
            nb  += b0.x*b0.x + b0.y*b0.y + b0.z*b0.z + b0.w*b0.w;

            dot += a1.x*b1.x + a1.y*b1.y + a1.z*b1.z + a1.w*b1.w;
            na  += a1.x*a1.x + a1.y*a1.y + a1.z*a1.z + a1.w*a1.w;
            nb  += b1.x*b1.x + b1.y*b1.y + b1.z*b1.z + b1.w*b1.w;
        }

        // Warp-local reduction (no block barriers in the hot loop).
        #pragma unroll
        for (int o = 16; o > 0; o >>= 1) {
            dot += __shfl_xor_sync(0xffffffffu, dot, o);
            na  += __shfl_xor_sync(0xffffffffu, na,  o);
            nb  += __shfl_xor_sync(0xffffffffu, nb,  o);
        }

        csum += dot * rsqrtf(na * nb);
    }

    // ── Per-CTA publish: ONE smem reduce + ONE fence + ONE atomic ──
    __shared__ float swarp[8];
    __shared__ bool  s_is_last;
    if (lane == 0) swarp[warp] = csum;
    __syncthreads();

    if (t == 0) {
        float bs = 0.f;
        #pragma unroll
        for (int i = 0; i < 8; i++) bs += swarp[i];
        g_partial[blockIdx.x] = bs;
        __threadfence();                               // publish before arrive
        unsigned int old = atomicAdd(&g_counter, 1u);
        s_is_last = (old == (unsigned)(GRID - 1));
    }
    __syncthreads();

    if (!s_is_last) return;

    // ── Last CTA: deterministic reduce of 1024 partials (L2-resident) ──
    __threadfence();
    float s = __ldcg(&g_partial[t]) + __ldcg(&g_partial[t + TPB])
            + __ldcg(&g_partial[t + 2 * TPB]) + __ldcg(&g_partial[t + 3 * TPB]);

    #pragma unroll
    for (int o = 16; o > 0; o >>= 1)
        s += __shfl_xor_sync(0xffffffffu, s, o);

    if (lane == 0) swarp[warp] = s;
    __syncthreads();

    if (t == 0) {
        float tot = 0.f;
        #pragma unroll
        for (int i = 0; i < 8; i++) tot += swarp[i];
        out[0] = 1.0f - tot / (float)NROWS;
        g_counter = 0;                                  // reset for replay
    }
}

extern "C" void kernel_launch(void* const* d_in, const int* in_sizes, int n_in,
                              void* d_out, int out_size)
{
    const float* cxr = (const float*)d_in[0];
    const float* ehr = (const float*)d_in[1];
    float* out = (float*)d_out;
    cosine_loss_persistent<<<GRID, TPB>>>(cxr, ehr, out);
}

// round 5
// speedup vs baseline: 1.1874x; 1.1874x over previous
#include <cuda_runtime.h>

#define NROWS 16384
#define DCOLS 2048
#define TPB   256

// Device-global scratch (no allocations allowed).
__device__ float        g_row_cos[NROWS];
__device__ unsigned int g_counter = 0;   // waiter resets -> replay-safe

__global__ void __launch_bounds__(TPB) cosine_loss_kernel(
    const float* __restrict__ cxr, const float* __restrict__ ehr,
    float* __restrict__ out)
{
    const int t    = threadIdx.x;
    const int lane = t & 31;
    const int warp = t >> 5;
    __shared__ float sdot[8], sna[8], snb[8];

    if (blockIdx.x < NROWS) {
        // ── Worker: one block per row (proven R1 mainloop) ──
        const int row = blockIdx.x;
        const float4* __restrict__ a = reinterpret_cast<const float4*>(ehr + (size_t)row * DCOLS);
        const float4* __restrict__ b = reinterpret_cast<const float4*>(cxr + (size_t)row * DCOLS);

        // 512 float4 per tensor; 256 threads -> 2 each. Streaming loads
        // (read-once data, keep L2 clean), all 4 front-batched for MLP.
        float4 a0 = __ldcs(&a[t]);
        float4 b0 = __ldcs(&b[t]);
        float4 a1 = __ldcs(&a[t + TPB]);
        float4 b1 = __ldcs(&b[t + TPB]);

        float dot, na, nb;
        dot  = a0.x*b0.x + a0.y*b0.y + a0.z*b0.z + a0.w*b0.w;
        na   = a0.x*a0.x + a0.y*a0.y + a0.z*a0.z + a0.w*a0.w;
        nb   = b0.x*b0.x + b0.y*b0.y + b0.z*b0.z + b0.w*b0.w;
        dot += a1.x*b1.x + a1.y*b1.y + a1.z*b1.z + a1.w*b1.w;
        na  += a1.x*a1.x + a1.y*a1.y + a1.z*a1.z + a1.w*a1.w;
        nb  += b1.x*b1.x + b1.y*b1.y + b1.z*b1.z + b1.w*b1.w;

        #pragma unroll
        for (int o = 16; o > 0; o >>= 1) {
            dot += __shfl_xor_sync(0xffffffffu, dot, o);
            na  += __shfl_xor_sync(0xffffffffu, na,  o);
            nb  += __shfl_xor_sync(0xffffffffu, nb,  o);
        }

        if (lane == 0) { sdot[warp] = dot; sna[warp] = na; snb[warp] = nb; }
        __syncthreads();

        if (t == 0) {
            float d = 0.f, x = 0.f, y = 0.f;
            #pragma unroll
            for (int i = 0; i < 8; i++) { d += sdot[i]; x += sna[i]; y += snb[i]; }
            g_row_cos[row] = d * rsqrtf(x * y);
            __threadfence();                 // publish row cos before arrive
            atomicAdd(&g_counter, 1u);       // result unused -> RED, no wait
        }
        return;                              // CTA retires immediately
    }

    // ── Waiter CTA (blockIdx.x == NROWS): spin, then final reduce ──
    if (t == 0) {
        while (*(volatile unsigned int*)&g_counter != (unsigned)NROWS)
            __nanosleep(128);
    }
    __syncthreads();
    __threadfence();   // acquire: order counter-observation before data reads

    const float4* rc = reinterpret_cast<const float4*>(g_row_cos);
    float s = 0.f;
    // 4096 float4 over 256 threads -> 16 each; L2-resident, bypass L1.
    #pragma unroll
    for (int i = 0; i < 16; i++) {
        float4 v = __ldcg(&rc[t + i * TPB]);
        s += v.x + v.y + v.z + v.w;
    }

    #pragma unroll
    for (int o = 16; o > 0; o >>= 1)
        s += __shfl_xor_sync(0xffffffffu, s, o);

    if (lane == 0) sdot[warp] = s;
    __syncthreads();

    if (t == 0) {
        float tot = 0.f;
        #pragma unroll
        for (int i = 0; i < 8; i++) tot += sdot[i];
        out[0] = 1.0f - tot / (float)NROWS;
        __threadfence();
        g_counter = 0;                       // reset for next graph replay
    }
}

extern "C" void kernel_launch(void* const* d_in, const int* in_sizes, int n_in,
                              void* d_out, int out_size)
{
    const float* cxr = (const float*)d_in[0];
    const float* ehr = (const float*)d_in[1];
    float* out = (float*)d_out;
    cosine_loss_kernel<<<NROWS + 1, TPB>>>(cxr, ehr, out);
}

// round 6
// speedup vs baseline: 1.2346x; 1.0397x over previous
#include <cuda_runtime.h>

#define NROWS 16384
#define DCOLS 2048
#define TPB   256

// Device-global scratch (no allocations allowed).
__device__ float        g_row_cos[NROWS];
__device__ unsigned int g_counter = 0;   // waiter resets -> replay-safe

__device__ __forceinline__ void red_release_add(unsigned int* p, unsigned int v) {
    // Fire-and-forget release reduction: orders prior STG (row cos) before the
    // counter bump at L2 scope, WITHOUT a full gpu membar on the retire path.
    asm volatile("red.release.gpu.global.add.u32 [%0], %1;" :: "l"(p), "r"(v) : "memory");
}

__device__ __forceinline__ unsigned int ld_acquire(const unsigned int* p) {
    unsigned int v;
    asm volatile("ld.acquire.gpu.global.u32 %0, [%1];" : "=r"(v) : "l"(p) : "memory");
    return v;
}

__global__ void __launch_bounds__(TPB) cosine_loss_kernel(
    const float* __restrict__ cxr, const float* __restrict__ ehr,
    float* __restrict__ out)
{
    const int t    = threadIdx.x;
    const int lane = t & 31;
    const int warp = t >> 5;
    __shared__ float sdot[8], sna[8], snb[8];

    if (blockIdx.x < NROWS) {
        // ── Worker: one block per row (proven mainloop, BW-wall limited) ──
        const int row = blockIdx.x;
        const float4* __restrict__ a = reinterpret_cast<const float4*>(ehr + (size_t)row * DCOLS);
        const float4* __restrict__ b = reinterpret_cast<const float4*>(cxr + (size_t)row * DCOLS);

        // 512 float4 per tensor; 256 threads -> 2 each; streaming (read-once),
        // all 4 loads front-batched for MLP.
        float4 a0 = __ldcs(&a[t]);
        float4 b0 = __ldcs(&b[t]);
        float4 a1 = __ldcs(&a[t + TPB]);
        float4 b1 = __ldcs(&b[t + TPB]);

        float dot, na, nb;
        dot  = a0.x*b0.x + a0.y*b0.y + a0.z*b0.z + a0.w*b0.w;
        na   = a0.x*a0.x + a0.y*a0.y + a0.z*a0.z + a0.w*a0.w;
        nb   = b0.x*b0.x + b0.y*b0.y + b0.z*b0.z + b0.w*b0.w;
        dot += a1.x*b1.x + a1.y*b1.y + a1.z*b1.z + a1.w*b1.w;
        na  += a1.x*a1.x + a1.y*a1.y + a1.z*a1.z + a1.w*a1.w;
        nb  += b1.x*b1.x + b1.y*b1.y + b1.z*b1.z + b1.w*b1.w;

        #pragma unroll
        for (int o = 16; o > 0; o >>= 1) {
            dot += __shfl_xor_sync(0xffffffffu, dot, o);
            na  += __shfl_xor_sync(0xffffffffu, na,  o);
            nb  += __shfl_xor_sync(0xffffffffu, nb,  o);
        }

        if (lane == 0) { sdot[warp] = dot; sna[warp] = na; snb[warp] = nb; }
        __syncthreads();

        if (t == 0) {
            float d = 0.f, x = 0.f, y = 0.f;
            #pragma unroll
            for (int i = 0; i < 8; i++) { d += sdot[i]; x += sna[i]; y += snb[i]; }
            g_row_cos[row] = d * rsqrtf(x * y);
            red_release_add(&g_counter, 1u);   // release RED: no membar, no wait
        }
        return;                                 // CTA retires immediately
    }

    // ── Waiter CTA (blockIdx.x == NROWS, scheduled last): spin + reduce ──
    if (t == 0) {
        while (ld_acquire(&g_counter) != (unsigned)NROWS)
            __nanosleep(64);
    }
    __syncthreads();   // broadcasts the acquire-observation to all threads

    const float4* rc = reinterpret_cast<const float4*>(g_row_cos);
    float s = 0.f;
    // 4096 float4 over 256 threads -> 16 each; L2-resident; batch 4-deep MLP.
    #pragma unroll
    for (int i = 0; i < 4; i++) {
        float4 v0 = __ldcg(&rc[t + (4*i + 0) * TPB]);
        float4 v1 = __ldcg(&rc[t + (4*i + 1) * TPB]);
        float4 v2 = __ldcg(&rc[t + (4*i + 2) * TPB]);
        float4 v3 = __ldcg(&rc[t + (4*i + 3) * TPB]);
        s += v0.x + v0.y + v0.z + v0.w;
        s += v1.x + v1.y + v1.z + v1.w;
        s += v2.x + v2.y + v2.z + v2.w;
        s += v3.x + v3.y + v3.z + v3.w;
    }

    #pragma unroll
    for (int o = 16; o > 0; o >>= 1)
        s += __shfl_xor_sync(0xffffffffu, s, o);

    if (lane == 0) sdot[warp] = s;
    __syncthreads();

    if (t == 0) {
        float tot = 0.f;
        #pragma unroll
        for (int i = 0; i < 8; i++) tot += sdot[i];
        out[0] = 1.0f - tot / (float)NROWS;
        __threadfence();
        g_counter = 0;                          // reset for next graph replay
    }
}

extern "C" void kernel_launch(void* const* d_in, const int* in_sizes, int n_in,
                              void* d_out, int out_size)
{
    const float* cxr = (const float*)d_in[0];
    const float* ehr = (const float*)d_in[1];
    float* out = (float*)d_out;
    cosine_loss_kernel<<<NROWS + 1, TPB>>>(cxr, ehr, out);
}